// round 8
// baseline (speedup 1.0000x reference)
#include <cuda_runtime.h>
#include <cuda_bf16.h>
#include <cstdint>

#define NB   256
#define LAT  20
#define HID  128
#define NG   25000
#define NGB  1000
#define NC   7

// output tuple (mu, theta, pi_drop, sample, pi) concatenated, fp32
#define OFF_MU      0
#define OFF_THETA   6400000
#define OFF_PD      12800000
#define OFF_SAMPLE  19200000
#define OFF_PI      25600000

// scratch (device globals; no allocations allowed)
__device__ __align__(16) float g_xt[HID * NB];   // x^T[h][b]
// per (b,o): floats [0..6]=p, [8..14]=log(p+1e-20), padded to 16 for LDG.128
__device__ __align__(16) float g_pp[NB * NGB * 16];

// ---------------------------------------------------------------------------
// packed fp32x2 helpers (Blackwell FFMA2 — IEEE-exact lanewise, 2 FMA / issue)
// ---------------------------------------------------------------------------
typedef unsigned long long F2;
__device__ __forceinline__ F2 pack2(float lo, float hi) {
  F2 r; asm("mov.b64 %0, {%1, %2};" : "=l"(r) : "f"(lo), "f"(hi)); return r;
}
__device__ __forceinline__ void unpack2(F2 v, float& lo, float& hi) {
  asm("mov.b64 {%0, %1}, %2;" : "=f"(lo), "=f"(hi) : "l"(v));
}
__device__ __forceinline__ F2 ffma2(F2 a, F2 b, F2 c) {
  F2 d; asm("fma.rn.f32x2 %0, %1, %2, %3;" : "=l"(d) : "l"(a), "l"(b), "l"(c));
  return d;
}

// ---------------------------------------------------------------------------
// K1: x = relu(bn(relu(bn(z@w0+b0)) @ w1 + b1)) -> g_xt (k-major)
// ---------------------------------------------------------------------------
__global__ __launch_bounds__(HID) void k_mlp(
    const float* __restrict__ z,  const float* __restrict__ w0,
    const float* __restrict__ b0, const float* __restrict__ g0,
    const float* __restrict__ be0,const float* __restrict__ m0,
    const float* __restrict__ v0,
    const float* __restrict__ w1, const float* __restrict__ b1,
    const float* __restrict__ g1, const float* __restrict__ be1,
    const float* __restrict__ m1, const float* __restrict__ v1) {
  __shared__ float zs[LAT];
  __shared__ float xs[HID];
  const int b = blockIdx.x;
  const int h = threadIdx.x;
  if (h < LAT) zs[h] = z[b * LAT + h];
  __syncthreads();
  float acc = b0[h];
#pragma unroll
  for (int k = 0; k < LAT; k++) acc = fmaf(zs[k], w0[k * HID + h], acc);
  acc = (acc - m0[h]) * rsqrtf(v0[h] + 1e-3f) * g0[h] + be0[h];
  acc = fmaxf(acc, 0.0f);
  xs[h] = acc;
  __syncthreads();
  float a2 = b1[h];
#pragma unroll
  for (int k = 0; k < HID; k++) a2 = fmaf(xs[k], w1[k * HID + h], a2);
  a2 = (a2 - m1[h]) * rsqrtf(v1[h] + 1e-3f) * g1[h] + be1[h];
  a2 = fmaxf(a2, 0.0f);
  g_xt[h * NB + b] = a2;
}

// ---------------------------------------------------------------------------
// K2: theta = exp(x@wr+br), pi_drop = x@wd+bd
// BM=128 x BN=64 x BK=32, 256 threads, thread tile 8b x 4g x 2 matrices.
// ---------------------------------------------------------------------------
#define BM 128
#define BN 64
#define BK 32
__global__ __launch_bounds__(256) void k_gemm(
    const float* __restrict__ wr, const float* __restrict__ br,
    const float* __restrict__ wd, const float* __restrict__ bd,
    float* __restrict__ out) {
  __shared__ float xs[BK][BM];    // 16 KB, [k][m], conflict-free both phases
  __shared__ float wrs[BK][BN];   // 8 KB
  __shared__ float wds[BK][BN];   // 8 KB
  const int tid = threadIdx.x;
  const int tx = tid & 15;        // gene group (4 genes)
  const int ty = tid >> 4;        // batch group (8 batches)
  const int g0 = blockIdx.x * BN;
  const int m0 = blockIdx.y * BM;

  F2 aT2[8][2], aD2[8][2];
#pragma unroll
  for (int i = 0; i < 8; i++) {
    aT2[i][0] = aT2[i][1] = 0ull;
    aD2[i][0] = aD2[i][1] = 0ull;
  }

  for (int kc = 0; kc < HID; kc += BK) {
    {
      const int m4 = (tid & 31) * 4;
      const int kk0 = tid >> 5;
#pragma unroll
      for (int t = 0; t < 4; t++) {
        const int kk = kk0 + t * 8;
        *(float4*)&xs[kk][m4] =
            *(const float4*)&g_xt[(kc + kk) * NB + m0 + m4];
      }
    }
    {
      const int j4 = (tid & 15) * 4;
      const int kk0 = tid >> 4;
#pragma unroll
      for (int t = 0; t < 2; t++) {
        const int kk = kk0 + t * 16;
        const int g = g0 + j4;
        float4 vr, vd;
        if (g + 3 < NG) {
          vr = *(const float4*)&wr[(size_t)(kc + kk) * NG + g];
          vd = *(const float4*)&wd[(size_t)(kc + kk) * NG + g];
        } else {
          float r[4], d[4];
#pragma unroll
          for (int q = 0; q < 4; q++) {
            const bool ok = (g + q < NG);
            r[q] = ok ? wr[(size_t)(kc + kk) * NG + g + q] : 0.0f;
            d[q] = ok ? wd[(size_t)(kc + kk) * NG + g + q] : 0.0f;
          }
          vr = make_float4(r[0], r[1], r[2], r[3]);
          vd = make_float4(d[0], d[1], d[2], d[3]);
        }
        *(float4*)&wrs[kk][j4] = vr;
        *(float4*)&wds[kk][j4] = vd;
      }
    }
    __syncthreads();
#pragma unroll
    for (int k = 0; k < BK; k++) {
      const float4 a0 = *(const float4*)&xs[k][ty * 8];
      const float4 a1 = *(const float4*)&xs[k][ty * 8 + 4];
      const F2 w0 = *(const F2*)&wrs[k][tx * 4];
      const F2 w1 = *(const F2*)&wrs[k][tx * 4 + 2];
      const F2 d0 = *(const F2*)&wds[k][tx * 4];
      const F2 d1 = *(const F2*)&wds[k][tx * 4 + 2];
      const float a[8] = {a0.x, a0.y, a0.z, a0.w, a1.x, a1.y, a1.z, a1.w};
#pragma unroll
      for (int i = 0; i < 8; i++) {
        const F2 ap = pack2(a[i], a[i]);
        aT2[i][0] = ffma2(ap, w0, aT2[i][0]);
        aT2[i][1] = ffma2(ap, w1, aT2[i][1]);
        aD2[i][0] = ffma2(ap, d0, aD2[i][0]);
        aD2[i][1] = ffma2(ap, d1, aD2[i][1]);
      }
    }
    __syncthreads();
  }

  const int gbase = g0 + tx * 4;
  const bool full = (gbase + 3 < NG);
  float brv[4] = {}, bdv[4] = {};
#pragma unroll
  for (int q = 0; q < 4; q++)
    if (gbase + q < NG) { brv[q] = br[gbase + q]; bdv[q] = bd[gbase + q]; }
#pragma unroll
  for (int i = 0; i < 8; i++) {
    float t[4], d[4];
    unpack2(aT2[i][0], t[0], t[1]); unpack2(aT2[i][1], t[2], t[3]);
    unpack2(aD2[i][0], d[0], d[1]); unpack2(aD2[i][1], d[2], d[3]);
    const int mrow = m0 + ty * 8 + i;
    const size_t idx = (size_t)mrow * NG + gbase;
    if (full) {
      float4 to = make_float4(__expf(t[0] + brv[0]), __expf(t[1] + brv[1]),
                              __expf(t[2] + brv[2]), __expf(t[3] + brv[3]));
      float4 po = make_float4(d[0] + bdv[0], d[1] + bdv[1],
                              d[2] + bdv[2], d[3] + bdv[3]);
      *(float4*)&out[OFF_THETA + idx] = to;
      *(float4*)&out[OFF_PD + idx]    = po;
    } else {
#pragma unroll
      for (int q = 0; q < 4; q++) {
        if (gbase + q >= NG) continue;
        out[OFF_THETA + idx + q] = __expf(t[q] + brv[q]);
        out[OFF_PD + idx + q]    = d[q] + bdv[q];
      }
    }
  }
}

// ---------------------------------------------------------------------------
// K3: rho[c][b][o] = x@wrho[c] + brho[c]; softmax over c; store p / log(p+eps)
// ---------------------------------------------------------------------------
__global__ __launch_bounds__(256) void k_rho(
    const float* __restrict__ wrho, const float* __restrict__ brho) {
  __shared__ float ws[NC * HID * 8];  // [c][h][j] contiguous = 28 KB
  const int tid = threadIdx.x;
  const int b = tid;
  const int o0 = blockIdx.x * 8;
  for (int idx = tid; idx < NC * HID * 8; idx += 256) {
    const int c = idx >> 10;
    const int rem = idx & 1023;
    const int h = rem >> 3, j = rem & 7;
    ws[idx] = wrho[c * HID * NGB + h * NGB + o0 + j];
  }
  __syncthreads();

  F2 acc2[NC][4];
#pragma unroll
  for (int c = 0; c < NC; c++)
#pragma unroll
    for (int q = 0; q < 4; q++) acc2[c][q] = 0ull;

  for (int h = 0; h < HID; h++) {
    const float xv = g_xt[h * NB + b];
    const F2 xp = pack2(xv, xv);
#pragma unroll
    for (int c = 0; c < NC; c++) {
      const F2* wp = (const F2*)&ws[(c * HID + h) * 8];
      acc2[c][0] = ffma2(xp, wp[0], acc2[c][0]);
      acc2[c][1] = ffma2(xp, wp[1], acc2[c][1]);
      acc2[c][2] = ffma2(xp, wp[2], acc2[c][2]);
      acc2[c][3] = ffma2(xp, wp[3], acc2[c][3]);
    }
  }
  float acc[NC][8];
#pragma unroll
  for (int c = 0; c < NC; c++)
#pragma unroll
    for (int q = 0; q < 4; q++) unpack2(acc2[c][q], acc[c][2 * q], acc[c][2 * q + 1]);

#pragma unroll
  for (int j = 0; j < 8; j++) {
    float v[NC];
    float m = -3.0e38f;
#pragma unroll
    for (int c = 0; c < NC; c++) {
      v[c] = acc[c][j] + brho[c * NGB + o0 + j];
      m = fmaxf(m, v[c]);
    }
    float e[NC], sum = 0.0f;
#pragma unroll
    for (int c = 0; c < NC; c++) { e[c] = expf(v[c] - m); sum += e[c]; }
    const int base = (b * NGB + o0 + j) * 16;
#pragma unroll
    for (int c = 0; c < NC; c++) {
      const float p = e[c] / sum;
      g_pp[base + c]     = p;
      g_pp[base + 8 + c] = logf(p + 1e-20f);
    }
    g_pp[base + 7] = 0.0f; g_pp[base + 15] = 0.0f;
  }
}

// ---------------------------------------------------------------------------
// K5: pi output writer — memory-bound, coalesced STG.128, overlaps k_sample.
// pi[b][g][c] = g_pp[(b*NGB + g/25)*16 + c]
// ---------------------------------------------------------------------------
__global__ __launch_bounds__(256) void k_pi(float* __restrict__ out) {
  const unsigned i = (blockIdx.x * 256u + threadIdx.x) * 4u;  // < 44.8M
  float v[4];
#pragma unroll
  for (int q = 0; q < 4; q++) {
    const unsigned idx = i + q;
    const unsigned b   = idx / 175000u;
    const unsigned rem = idx - b * 175000u;
    const unsigned g   = rem / 7u;
    const unsigned c   = rem - g * 7u;
    const unsigned o   = g / 25u;
    v[q] = __ldg(&g_pp[(b * NGB + o) * 16u + c]);
  }
  *(float4*)&out[OFF_PI + i] = make_float4(v[0], v[1], v[2], v[3]);
}

// ---------------------------------------------------------------------------
// K4: Gumbel-softmax straight-through sampler -> sample, mu only
// threefry2x32, key=(0,42), partitionable counters: bits[i] = o0 ^ o1
// ---------------------------------------------------------------------------
__device__ __forceinline__ unsigned tf_bits(unsigned ctr) {
  const unsigned k0 = 0u, k1 = 42u, k2 = 0x1BD11BDAu ^ 0u ^ 42u;
  unsigned x0 = 0u + k0;      // counts_hi = 0
  unsigned x1 = ctr + k1;     // counts_lo = ctr
#define TF_R(r) { x0 += x1; x1 = __funnelshift_l(x1, x1, r); x1 ^= x0; }
  TF_R(13) TF_R(15) TF_R(26) TF_R(6)   x0 += k1; x1 += k2 + 1u;
  TF_R(17) TF_R(29) TF_R(16) TF_R(24)  x0 += k2; x1 += k0 + 2u;
  TF_R(13) TF_R(15) TF_R(26) TF_R(6)   x0 += k0; x1 += k1 + 3u;
  TF_R(17) TF_R(29) TF_R(16) TF_R(24)  x0 += k1; x1 += k2 + 4u;
  TF_R(13) TF_R(15) TF_R(26) TF_R(6)   x0 += k2; x1 += k0 + 5u;
#undef TF_R
  return x0 ^ x1;
}

__global__ __launch_bounds__(128) void k_sample(
    const float* __restrict__ wsc, const float* __restrict__ bsc,
    float* __restrict__ out) {
  const int b = blockIdx.y;
  const int g = blockIdx.x * 128 + threadIdx.x;
  if (g >= NG) return;
  const int o = g / 25;
  const float4* pp = (const float4*)&g_pp[(b * NGB + o) * 16];
  const float4 lv0 = __ldg(pp + 2), lv1 = __ldg(pp + 3);
  const float lp[NC] = {lv0.x, lv0.y, lv0.z, lv0.w, lv1.x, lv1.y, lv1.z};
  const unsigned i0 = (unsigned)(b * NG + g) * 7u;

  float s[NC];
  float m = -3.0e38f;
#pragma unroll
  for (int c = 0; c < NC; c++) {
    const unsigned bits = tf_bits(i0 + (unsigned)c);
    const float u = __uint_as_float((bits >> 9) | 0x3f800000u) - 1.0f;
    const float gn = -__logf(-__logf(u + 1e-20f) + 1e-20f);
    const float sv = (lp[c] + gn) * 10.0f;  // /TEMP, TEMP=0.1
    s[c] = sv;
    m = fmaxf(m, sv);
  }
  float e[NC], sum = 0.0f;
#pragma unroll
  for (int c = 0; c < NC; c++) { e[c] = __expf(s[c] - m); sum += e[c]; }
  const float rinv = __fdividef(1.0f, sum);
  float y[NC], ym = 0.0f;
#pragma unroll
  for (int c = 0; c < NC; c++) { y[c] = e[c] * rinv; ym = fmaxf(ym, y[c]); }
  float smp = 0.0f;
#pragma unroll
  for (int c = 0; c < NC; c++) {
    const float yh = (y[c] == ym) ? 1.0f : 0.0f;
    smp += (float)c * ((yh - y[c]) + y[c]);   // straight-through forward value
  }
  const size_t bg = (size_t)b * NG + g;
  out[OFF_SAMPLE + bg] = smp;
  const float t = smp * wsc[g] + bsc[g];
  out[OFF_MU + bg] = __fdividef(1.0f, 1.0f + __expf(-t));
}

// ---------------------------------------------------------------------------
extern "C" void kernel_launch(void* const* d_in, const int* in_sizes, int n_in,
                              void* d_out, int out_size) {
  const float* z   = (const float*)d_in[0];
  const float* w0  = (const float*)d_in[1];
  const float* b0  = (const float*)d_in[2];
  const float* g0  = (const float*)d_in[3];
  const float* be0 = (const float*)d_in[4];
  const float* m0  = (const float*)d_in[5];
  const float* v0  = (const float*)d_in[6];
  const float* w1  = (const float*)d_in[7];
  const float* b1  = (const float*)d_in[8];
  const float* g1  = (const float*)d_in[9];
  const float* be1 = (const float*)d_in[10];
  const float* m1  = (const float*)d_in[11];
  const float* v1  = (const float*)d_in[12];
  const float* wr  = (const float*)d_in[13];
  const float* br  = (const float*)d_in[14];
  const float* wd  = (const float*)d_in[15];
  const float* bd  = (const float*)d_in[16];
  const float* wrho= (const float*)d_in[17];
  const float* brho= (const float*)d_in[18];
  const float* wsc = (const float*)d_in[19];
  const float* bsc = (const float*)d_in[20];
  float* out = (float*)d_out;

  // one-time side streams + events (created outside capture: the harness
  // runs kernel_launch once for correctness before capturing)
  static cudaStream_t s2 = nullptr, s3 = nullptr;
  static cudaEvent_t evR = nullptr, evJ2 = nullptr, evJ3 = nullptr;
  if (!s2) {
    cudaStreamCreateWithFlags(&s2, cudaStreamNonBlocking);
    cudaStreamCreateWithFlags(&s3, cudaStreamNonBlocking);
    cudaEventCreateWithFlags(&evR, cudaEventDisableTiming);
    cudaEventCreateWithFlags(&evJ2, cudaEventDisableTiming);
    cudaEventCreateWithFlags(&evJ3, cudaEventDisableTiming);
  }

  k_mlp<<<NB, HID>>>(z, w0, b0, g0, be0, m0, v0, w1, b1, g1, be1, m1, v1);
  k_rho<<<NGB / 8, 256>>>(wrho, brho);
  cudaEventRecord(evR, 0);

  // fork after rho: gemm (s2) and pi-writer (s3) overlap the sampler
  cudaStreamWaitEvent(s2, evR, 0);
  dim3 gg((NG + BN - 1) / BN, NB / BM);
  k_gemm<<<gg, 256, 0, s2>>>(wr, br, wd, bd, out);
  cudaEventRecord(evJ2, s2);

  cudaStreamWaitEvent(s3, evR, 0);
  k_pi<<<(NB * NG * NC) / (256 * 4), 256, 0, s3>>>(out);
  cudaEventRecord(evJ3, s3);

  dim3 gs((NG + 127) / 128, NB);
  k_sample<<<gs, 128>>>(wsc, bsc, out);

  // join
  cudaStreamWaitEvent(0, evJ2, 0);
  cudaStreamWaitEvent(0, evJ3, 0);
}

// round 9
// speedup vs baseline: 1.1519x; 1.1519x over previous
#include <cuda_runtime.h>
#include <cuda_bf16.h>
#include <cstdint>

#define NB   256
#define LAT  20
#define HID  128
#define NG   25000
#define NGB  1000
#define NC   7

// output tuple (mu, theta, pi_drop, sample, pi) concatenated, fp32
#define OFF_MU      0
#define OFF_THETA   6400000
#define OFF_PD      12800000
#define OFF_SAMPLE  19200000
#define OFF_PI      25600000

// scratch (device globals; no allocations allowed)
__device__ __align__(16) float g_xt[HID * NB];   // x^T[h][b]
// per (b,o): floats [0..6]=p, [8..14]=log(p+1e-20), padded to 16 for LDG.128
__device__ __align__(16) float g_pp[NB * NGB * 16];

// ---------------------------------------------------------------------------
// packed fp32x2 helpers (Blackwell FFMA2 — IEEE-exact lanewise, 2 FMA / issue)
// ---------------------------------------------------------------------------
typedef unsigned long long F2;
__device__ __forceinline__ F2 pack2(float lo, float hi) {
  F2 r; asm("mov.b64 %0, {%1, %2};" : "=l"(r) : "f"(lo), "f"(hi)); return r;
}
__device__ __forceinline__ void unpack2(F2 v, float& lo, float& hi) {
  asm("mov.b64 {%0, %1}, %2;" : "=f"(lo), "=f"(hi) : "l"(v));
}
__device__ __forceinline__ F2 ffma2(F2 a, F2 b, F2 c) {
  F2 d; asm("fma.rn.f32x2 %0, %1, %2, %3;" : "=l"(d) : "l"(a), "l"(b), "l"(c));
  return d;
}

// ---------------------------------------------------------------------------
// K1: x = relu(bn(relu(bn(z@w0+b0)) @ w1 + b1)) -> g_xt (k-major)
// ---------------------------------------------------------------------------
__global__ __launch_bounds__(HID) void k_mlp(
    const float* __restrict__ z,  const float* __restrict__ w0,
    const float* __restrict__ b0, const float* __restrict__ g0,
    const float* __restrict__ be0,const float* __restrict__ m0,
    const float* __restrict__ v0,
    const float* __restrict__ w1, const float* __restrict__ b1,
    const float* __restrict__ g1, const float* __restrict__ be1,
    const float* __restrict__ m1, const float* __restrict__ v1) {
  __shared__ float zs[LAT];
  __shared__ float xs[HID];
  const int b = blockIdx.x;
  const int h = threadIdx.x;
  if (h < LAT) zs[h] = z[b * LAT + h];
  __syncthreads();
  float acc = b0[h];
#pragma unroll
  for (int k = 0; k < LAT; k++) acc = fmaf(zs[k], w0[k * HID + h], acc);
  acc = (acc - m0[h]) * rsqrtf(v0[h] + 1e-3f) * g0[h] + be0[h];
  acc = fmaxf(acc, 0.0f);
  xs[h] = acc;
  __syncthreads();
  float a2 = b1[h];
#pragma unroll
  for (int k = 0; k < HID; k++) a2 = fmaf(xs[k], w1[k * HID + h], a2);
  a2 = (a2 - m1[h]) * rsqrtf(v1[h] + 1e-3f) * g1[h] + be1[h];
  a2 = fmaxf(a2, 0.0f);
  g_xt[h * NB + b] = a2;
}

// ---------------------------------------------------------------------------
// K2: theta = exp(x@wr+br), pi_drop = x@wd+bd
// BM=128 x BN=64 x BK=32, 256 threads, thread tile 8b x 4g x 2 matrices.
// ---------------------------------------------------------------------------
#define BM 128
#define BN 64
#define BK 32
__global__ __launch_bounds__(256) void k_gemm(
    const float* __restrict__ wr, const float* __restrict__ br,
    const float* __restrict__ wd, const float* __restrict__ bd,
    float* __restrict__ out) {
  __shared__ float xs[BK][BM];    // 16 KB, [k][m], conflict-free both phases
  __shared__ float wrs[BK][BN];   // 8 KB
  __shared__ float wds[BK][BN];   // 8 KB
  const int tid = threadIdx.x;
  const int tx = tid & 15;        // gene group (4 genes)
  const int ty = tid >> 4;        // batch group (8 batches)
  const int g0 = blockIdx.x * BN;
  const int m0 = blockIdx.y * BM;

  F2 aT2[8][2], aD2[8][2];
#pragma unroll
  for (int i = 0; i < 8; i++) {
    aT2[i][0] = aT2[i][1] = 0ull;
    aD2[i][0] = aD2[i][1] = 0ull;
  }

  for (int kc = 0; kc < HID; kc += BK) {
    {
      const int m4 = (tid & 31) * 4;
      const int kk0 = tid >> 5;
#pragma unroll
      for (int t = 0; t < 4; t++) {
        const int kk = kk0 + t * 8;
        *(float4*)&xs[kk][m4] =
            *(const float4*)&g_xt[(kc + kk) * NB + m0 + m4];
      }
    }
    {
      const int j4 = (tid & 15) * 4;
      const int kk0 = tid >> 4;
#pragma unroll
      for (int t = 0; t < 2; t++) {
        const int kk = kk0 + t * 16;
        const int g = g0 + j4;
        float4 vr, vd;
        if (g + 3 < NG) {
          vr = *(const float4*)&wr[(size_t)(kc + kk) * NG + g];
          vd = *(const float4*)&wd[(size_t)(kc + kk) * NG + g];
        } else {
          float r[4], d[4];
#pragma unroll
          for (int q = 0; q < 4; q++) {
            const bool ok = (g + q < NG);
            r[q] = ok ? wr[(size_t)(kc + kk) * NG + g + q] : 0.0f;
            d[q] = ok ? wd[(size_t)(kc + kk) * NG + g + q] : 0.0f;
          }
          vr = make_float4(r[0], r[1], r[2], r[3]);
          vd = make_float4(d[0], d[1], d[2], d[3]);
        }
        *(float4*)&wrs[kk][j4] = vr;
        *(float4*)&wds[kk][j4] = vd;
      }
    }
    __syncthreads();
#pragma unroll
    for (int k = 0; k < BK; k++) {
      const float4 a0 = *(const float4*)&xs[k][ty * 8];
      const float4 a1 = *(const float4*)&xs[k][ty * 8 + 4];
      const F2 w0 = *(const F2*)&wrs[k][tx * 4];
      const F2 w1 = *(const F2*)&wrs[k][tx * 4 + 2];
      const F2 d0 = *(const F2*)&wds[k][tx * 4];
      const F2 d1 = *(const F2*)&wds[k][tx * 4 + 2];
      const float a[8] = {a0.x, a0.y, a0.z, a0.w, a1.x, a1.y, a1.z, a1.w};
#pragma unroll
      for (int i = 0; i < 8; i++) {
        const F2 ap = pack2(a[i], a[i]);
        aT2[i][0] = ffma2(ap, w0, aT2[i][0]);
        aT2[i][1] = ffma2(ap, w1, aT2[i][1]);
        aD2[i][0] = ffma2(ap, d0, aD2[i][0]);
        aD2[i][1] = ffma2(ap, d1, aD2[i][1]);
      }
    }
    __syncthreads();
  }

  const int gbase = g0 + tx * 4;
  const bool full = (gbase + 3 < NG);
  float brv[4] = {}, bdv[4] = {};
#pragma unroll
  for (int q = 0; q < 4; q++)
    if (gbase + q < NG) { brv[q] = br[gbase + q]; bdv[q] = bd[gbase + q]; }
#pragma unroll
  for (int i = 0; i < 8; i++) {
    float t[4], d[4];
    unpack2(aT2[i][0], t[0], t[1]); unpack2(aT2[i][1], t[2], t[3]);
    unpack2(aD2[i][0], d[0], d[1]); unpack2(aD2[i][1], d[2], d[3]);
    const int mrow = m0 + ty * 8 + i;
    const size_t idx = (size_t)mrow * NG + gbase;
    if (full) {
      float4 to = make_float4(__expf(t[0] + brv[0]), __expf(t[1] + brv[1]),
                              __expf(t[2] + brv[2]), __expf(t[3] + brv[3]));
      float4 po = make_float4(d[0] + bdv[0], d[1] + bdv[1],
                              d[2] + bdv[2], d[3] + bdv[3]);
      *(float4*)&out[OFF_THETA + idx] = to;
      *(float4*)&out[OFF_PD + idx]    = po;
    } else {
#pragma unroll
      for (int q = 0; q < 4; q++) {
        if (gbase + q >= NG) continue;
        out[OFF_THETA + idx + q] = __expf(t[q] + brv[q]);
        out[OFF_PD + idx + q]    = d[q] + bdv[q];
      }
    }
  }
}

// ---------------------------------------------------------------------------
// K3: rho[c][b][o] = x@wrho[c] + brho[c]; softmax over c; store p / log(p+eps)
// ---------------------------------------------------------------------------
__global__ __launch_bounds__(256) void k_rho(
    const float* __restrict__ wrho, const float* __restrict__ brho) {
  __shared__ float ws[NC * HID * 8];  // [c][h][j] contiguous = 28 KB
  const int tid = threadIdx.x;
  const int b = tid;
  const int o0 = blockIdx.x * 8;
  for (int idx = tid; idx < NC * HID * 8; idx += 256) {
    const int c = idx >> 10;
    const int rem = idx & 1023;
    const int h = rem >> 3, j = rem & 7;
    ws[idx] = wrho[c * HID * NGB + h * NGB + o0 + j];
  }
  __syncthreads();

  F2 acc2[NC][4];
#pragma unroll
  for (int c = 0; c < NC; c++)
#pragma unroll
    for (int q = 0; q < 4; q++) acc2[c][q] = 0ull;

  for (int h = 0; h < HID; h++) {
    const float xv = g_xt[h * NB + b];
    const F2 xp = pack2(xv, xv);
#pragma unroll
    for (int c = 0; c < NC; c++) {
      const F2* wp = (const F2*)&ws[(c * HID + h) * 8];
      acc2[c][0] = ffma2(xp, wp[0], acc2[c][0]);
      acc2[c][1] = ffma2(xp, wp[1], acc2[c][1]);
      acc2[c][2] = ffma2(xp, wp[2], acc2[c][2]);
      acc2[c][3] = ffma2(xp, wp[3], acc2[c][3]);
    }
  }
  float acc[NC][8];
#pragma unroll
  for (int c = 0; c < NC; c++)
#pragma unroll
    for (int q = 0; q < 4; q++) unpack2(acc2[c][q], acc[c][2 * q], acc[c][2 * q + 1]);

#pragma unroll
  for (int j = 0; j < 8; j++) {
    float v[NC];
    float m = -3.0e38f;
#pragma unroll
    for (int c = 0; c < NC; c++) {
      v[c] = acc[c][j] + brho[c * NGB + o0 + j];
      m = fmaxf(m, v[c]);
    }
    float e[NC], sum = 0.0f;
#pragma unroll
    for (int c = 0; c < NC; c++) { e[c] = expf(v[c] - m); sum += e[c]; }
    const int base = (b * NGB + o0 + j) * 16;
#pragma unroll
    for (int c = 0; c < NC; c++) {
      const float p = e[c] / sum;
      g_pp[base + c]     = p;
      g_pp[base + 8 + c] = logf(p + 1e-20f);
    }
    g_pp[base + 7] = 0.0f; g_pp[base + 15] = 0.0f;
  }
}

// ---------------------------------------------------------------------------
// K4: Gumbel argmax sampler + mu + pi output
// threefry2x32, key=(0,42), partitionable counters: bits[i] = o0 ^ o1.
// Straight-through identity: for non-argmax c, (0-y)+y == 0 exactly in fp32,
// so sample = cmax * ((1-ymax)+ymax) = cmax * (1 +- 1ulp). We emit (float)cmax
// (error ~1e-7, argmax-preserving) and skip the softmax entirely.
// ---------------------------------------------------------------------------
__device__ __forceinline__ unsigned tf_bits(unsigned ctr) {
  const unsigned k0 = 0u, k1 = 42u, k2 = 0x1BD11BDAu ^ 0u ^ 42u;
  unsigned x0 = 0u + k0;      // counts_hi = 0
  unsigned x1 = ctr + k1;     // counts_lo = ctr
#define TF_R(r) { x0 += x1; x1 = __funnelshift_l(x1, x1, r); x1 ^= x0; }
  TF_R(13) TF_R(15) TF_R(26) TF_R(6)   x0 += k1; x1 += k2 + 1u;
  TF_R(17) TF_R(29) TF_R(16) TF_R(24)  x0 += k2; x1 += k0 + 2u;
  TF_R(13) TF_R(15) TF_R(26) TF_R(6)   x0 += k0; x1 += k1 + 3u;
  TF_R(17) TF_R(29) TF_R(16) TF_R(24)  x0 += k1; x1 += k2 + 4u;
  TF_R(13) TF_R(15) TF_R(26) TF_R(6)   x0 += k2; x1 += k0 + 5u;
#undef TF_R
  return x0 ^ x1;
}

__global__ __launch_bounds__(128) void k_sample(
    const float* __restrict__ wsc, const float* __restrict__ bsc,
    float* __restrict__ out) {
  const int b = blockIdx.y;
  const int g = blockIdx.x * 128 + threadIdx.x;
  if (g >= NG) return;
  const int o = g / 25;
  const float4* pp = (const float4*)&g_pp[(b * NGB + o) * 16];
  const float4 pv0 = __ldg(pp + 0), pv1 = __ldg(pp + 1);
  const float4 lv0 = __ldg(pp + 2), lv1 = __ldg(pp + 3);
  const float p[NC]  = {pv0.x, pv0.y, pv0.z, pv0.w, pv1.x, pv1.y, pv1.z};
  const float lp[NC] = {lv0.x, lv0.y, lv0.z, lv0.w, lv1.x, lv1.y, lv1.z};
  const unsigned i0 = (unsigned)(b * NG + g) * 7u;

  float m = -3.0e38f;
  int cmax = 0;
#pragma unroll
  for (int c = 0; c < NC; c++) {
    const unsigned bits = tf_bits(i0 + (unsigned)c);
    const float u = __uint_as_float((bits >> 9) | 0x3f800000u) - 1.0f;
    const float gn = -__logf(-__logf(u + 1e-20f) + 1e-20f);
    const float sv = lp[c] + gn;      // *10 and softmax are argmax-invariant
    if (sv > m) { m = sv; cmax = c; }
  }
  const float smp = (float)cmax;
  const size_t bg = (size_t)b * NG + g;
  out[OFF_SAMPLE + bg] = smp;
  const float t = smp * wsc[g] + bsc[g];
  out[OFF_MU + bg] = __fdividef(1.0f, 1.0f + __expf(-t));
  float* po = out + OFF_PI + bg * 7;
#pragma unroll
  for (int c = 0; c < NC; c++) po[c] = p[c];
}

// ---------------------------------------------------------------------------
extern "C" void kernel_launch(void* const* d_in, const int* in_sizes, int n_in,
                              void* d_out, int out_size) {
  const float* z   = (const float*)d_in[0];
  const float* w0  = (const float*)d_in[1];
  const float* b0  = (const float*)d_in[2];
  const float* g0  = (const float*)d_in[3];
  const float* be0 = (const float*)d_in[4];
  const float* m0  = (const float*)d_in[5];
  const float* v0  = (const float*)d_in[6];
  const float* w1  = (const float*)d_in[7];
  const float* b1  = (const float*)d_in[8];
  const float* g1  = (const float*)d_in[9];
  const float* be1 = (const float*)d_in[10];
  const float* m1  = (const float*)d_in[11];
  const float* v1  = (const float*)d_in[12];
  const float* wr  = (const float*)d_in[13];
  const float* br  = (const float*)d_in[14];
  const float* wd  = (const float*)d_in[15];
  const float* bd  = (const float*)d_in[16];
  const float* wrho= (const float*)d_in[17];
  const float* brho= (const float*)d_in[18];
  const float* wsc = (const float*)d_in[19];
  const float* bsc = (const float*)d_in[20];
  float* out = (float*)d_out;

  k_mlp<<<NB, HID>>>(z, w0, b0, g0, be0, m0, v0, w1, b1, g1, be1, m1, v1);
  k_rho<<<NGB / 8, 256>>>(wrho, brho);
  dim3 gg((NG + BN - 1) / BN, NB / BM);
  k_gemm<<<gg, 256>>>(wr, br, wd, bd, out);
  dim3 gs((NG + 127) / 128, NB);
  k_sample<<<gs, 128>>>(wsc, bsc, out);
}

// round 11
// speedup vs baseline: 1.2406x; 1.0771x over previous
#include <cuda_runtime.h>
#include <cuda_bf16.h>
#include <cstdint>

#define NB   256
#define LAT  20
#define HID  128
#define NG   25000
#define NGB  1000
#define NC   7

// output tuple (mu, theta, pi_drop, sample, pi) concatenated, fp32
#define OFF_MU      0
#define OFF_THETA   6400000
#define OFF_PD      12800000
#define OFF_SAMPLE  19200000
#define OFF_PI      25600000

// scratch (device globals; no allocations allowed)
__device__ __align__(16) float g_xt[HID * NB];   // x^T[h][b]
// per (b,o): floats [0..6]=p, [8..14]=log(p+1e-20), padded to 16 for LDG.128
__device__ __align__(16) float g_pp[NB * NGB * 16];

// ---------------------------------------------------------------------------
// packed fp32x2 helpers (Blackwell FFMA2 — IEEE-exact lanewise, 2 FMA / issue)
// ---------------------------------------------------------------------------
typedef unsigned long long F2;
__device__ __forceinline__ F2 pack2(float lo, float hi) {
  F2 r; asm("mov.b64 %0, {%1, %2};" : "=l"(r) : "f"(lo), "f"(hi)); return r;
}
__device__ __forceinline__ void unpack2(F2 v, float& lo, float& hi) {
  asm("mov.b64 {%0, %1}, %2;" : "=f"(lo), "=f"(hi) : "l"(v));
}
__device__ __forceinline__ F2 ffma2(F2 a, F2 b, F2 c) {
  F2 d; asm("fma.rn.f32x2 %0, %1, %2, %3;" : "=l"(d) : "l"(a), "l"(b), "l"(c));
  return d;
}
// integer add routed to the fma pipe (IMAD) to offload the saturated alu pipe
__device__ __forceinline__ unsigned addf(unsigned a, unsigned b) {
  unsigned r;
  asm("mad.lo.u32 %0, %1, 1, %2;" : "=r"(r) : "r"(a), "r"(b));
  return r;
}

// ---------------------------------------------------------------------------
// K1: x = relu(bn(relu(bn(z@w0+b0)) @ w1 + b1)) -> g_xt (k-major)
// ---------------------------------------------------------------------------
__global__ __launch_bounds__(HID) void k_mlp(
    const float* __restrict__ z,  const float* __restrict__ w0,
    const float* __restrict__ b0, const float* __restrict__ g0,
    const float* __restrict__ be0,const float* __restrict__ m0,
    const float* __restrict__ v0,
    const float* __restrict__ w1, const float* __restrict__ b1,
    const float* __restrict__ g1, const float* __restrict__ be1,
    const float* __restrict__ m1, const float* __restrict__ v1) {
  __shared__ float zs[LAT];
  __shared__ float xs[HID];
  const int b = blockIdx.x;
  const int h = threadIdx.x;
  if (h < LAT) zs[h] = z[b * LAT + h];
  __syncthreads();
  float acc = b0[h];
#pragma unroll
  for (int k = 0; k < LAT; k++) acc = fmaf(zs[k], w0[k * HID + h], acc);
  acc = (acc - m0[h]) * rsqrtf(v0[h] + 1e-3f) * g0[h] + be0[h];
  acc = fmaxf(acc, 0.0f);
  xs[h] = acc;
  __syncthreads();
  float a2 = b1[h];
#pragma unroll
  for (int k = 0; k < HID; k++) a2 = fmaf(xs[k], w1[k * HID + h], a2);
  a2 = (a2 - m1[h]) * rsqrtf(v1[h] + 1e-3f) * g1[h] + be1[h];
  a2 = fmaxf(a2, 0.0f);
  g_xt[h * NB + b] = a2;
}

// ---------------------------------------------------------------------------
// K2: theta = exp(x@wr+br), pi_drop = x@wd+bd
// BM=128 x BN=64 x BK=32, 256 threads, thread tile 8b x 4g x 2 matrices.
// ---------------------------------------------------------------------------
#define BM 128
#define BN 64
#define BK 32
__global__ __launch_bounds__(256) void k_gemm(
    const float* __restrict__ wr, const float* __restrict__ br,
    const float* __restrict__ wd, const float* __restrict__ bd,
    float* __restrict__ out) {
  __shared__ float xs[BK][BM];    // 16 KB, [k][m], conflict-free both phases
  __shared__ float wrs[BK][BN];   // 8 KB
  __shared__ float wds[BK][BN];   // 8 KB
  const int tid = threadIdx.x;
  const int tx = tid & 15;        // gene group (4 genes)
  const int ty = tid >> 4;        // batch group (8 batches)
  const int g0 = blockIdx.x * BN;
  const int m0 = blockIdx.y * BM;

  F2 aT2[8][2], aD2[8][2];
#pragma unroll
  for (int i = 0; i < 8; i++) {
    aT2[i][0] = aT2[i][1] = 0ull;
    aD2[i][0] = aD2[i][1] = 0ull;
  }

  for (int kc = 0; kc < HID; kc += BK) {
    {
      const int m4 = (tid & 31) * 4;
      const int kk0 = tid >> 5;
#pragma unroll
      for (int t = 0; t < 4; t++) {
        const int kk = kk0 + t * 8;
        *(float4*)&xs[kk][m4] =
            *(const float4*)&g_xt[(kc + kk) * NB + m0 + m4];
      }
    }
    {
      const int j4 = (tid & 15) * 4;
      const int kk0 = tid >> 4;
#pragma unroll
      for (int t = 0; t < 2; t++) {
        const int kk = kk0 + t * 16;
        const int g = g0 + j4;
        float4 vr, vd;
        if (g + 3 < NG) {
          vr = *(const float4*)&wr[(size_t)(kc + kk) * NG + g];
          vd = *(const float4*)&wd[(size_t)(kc + kk) * NG + g];
        } else {
          float r[4], d[4];
#pragma unroll
          for (int q = 0; q < 4; q++) {
            const bool ok = (g + q < NG);
            r[q] = ok ? wr[(size_t)(kc + kk) * NG + g + q] : 0.0f;
            d[q] = ok ? wd[(size_t)(kc + kk) * NG + g + q] : 0.0f;
          }
          vr = make_float4(r[0], r[1], r[2], r[3]);
          vd = make_float4(d[0], d[1], d[2], d[3]);
        }
        *(float4*)&wrs[kk][j4] = vr;
        *(float4*)&wds[kk][j4] = vd;
      }
    }
    __syncthreads();
#pragma unroll
    for (int k = 0; k < BK; k++) {
      const float4 a0 = *(const float4*)&xs[k][ty * 8];
      const float4 a1 = *(const float4*)&xs[k][ty * 8 + 4];
      const F2 w0 = *(const F2*)&wrs[k][tx * 4];
      const F2 w1 = *(const F2*)&wrs[k][tx * 4 + 2];
      const F2 d0 = *(const F2*)&wds[k][tx * 4];
      const F2 d1 = *(const F2*)&wds[k][tx * 4 + 2];
      const float a[8] = {a0.x, a0.y, a0.z, a0.w, a1.x, a1.y, a1.z, a1.w};
#pragma unroll
      for (int i = 0; i < 8; i++) {
        const F2 ap = pack2(a[i], a[i]);
        aT2[i][0] = ffma2(ap, w0, aT2[i][0]);
        aT2[i][1] = ffma2(ap, w1, aT2[i][1]);
        aD2[i][0] = ffma2(ap, d0, aD2[i][0]);
        aD2[i][1] = ffma2(ap, d1, aD2[i][1]);
      }
    }
    __syncthreads();
  }

  const int gbase = g0 + tx * 4;
  const bool full = (gbase + 3 < NG);
  float brv[4] = {}, bdv[4] = {};
#pragma unroll
  for (int q = 0; q < 4; q++)
    if (gbase + q < NG) { brv[q] = br[gbase + q]; bdv[q] = bd[gbase + q]; }
#pragma unroll
  for (int i = 0; i < 8; i++) {
    float t[4], d[4];
    unpack2(aT2[i][0], t[0], t[1]); unpack2(aT2[i][1], t[2], t[3]);
    unpack2(aD2[i][0], d[0], d[1]); unpack2(aD2[i][1], d[2], d[3]);
    const int mrow = m0 + ty * 8 + i;
    const size_t idx = (size_t)mrow * NG + gbase;
    if (full) {
      float4 to = make_float4(__expf(t[0] + brv[0]), __expf(t[1] + brv[1]),
                              __expf(t[2] + brv[2]), __expf(t[3] + brv[3]));
      float4 po = make_float4(d[0] + bdv[0], d[1] + bdv[1],
                              d[2] + bdv[2], d[3] + bdv[3]);
      *(float4*)&out[OFF_THETA + idx] = to;
      *(float4*)&out[OFF_PD + idx]    = po;
    } else {
#pragma unroll
      for (int q = 0; q < 4; q++) {
        if (gbase + q >= NG) continue;
        out[OFF_THETA + idx + q] = __expf(t[q] + brv[q]);
        out[OFF_PD + idx + q]    = d[q] + bdv[q];
      }
    }
  }
}

// ---------------------------------------------------------------------------
// K3: rho[c][b][o] = x@wrho[c] + brho[c]; softmax over c; store p / log(p+eps)
// ---------------------------------------------------------------------------
__global__ __launch_bounds__(256) void k_rho(
    const float* __restrict__ wrho, const float* __restrict__ brho) {
  __shared__ float ws[NC * HID * 8];  // [c][h][j] contiguous = 28 KB
  const int tid = threadIdx.x;
  const int b = tid;
  const int o0 = blockIdx.x * 8;
  for (int idx = tid; idx < NC * HID * 8; idx += 256) {
    const int c = idx >> 10;
    const int rem = idx & 1023;
    const int h = rem >> 3, j = rem & 7;
    ws[idx] = wrho[c * HID * NGB + h * NGB + o0 + j];
  }
  __syncthreads();

  F2 acc2[NC][4];
#pragma unroll
  for (int c = 0; c < NC; c++)
#pragma unroll
    for (int q = 0; q < 4; q++) acc2[c][q] = 0ull;

  for (int h = 0; h < HID; h++) {
    const float xv = g_xt[h * NB + b];
    const F2 xp = pack2(xv, xv);
#pragma unroll
    for (int c = 0; c < NC; c++) {
      const F2* wp = (const F2*)&ws[(c * HID + h) * 8];
      acc2[c][0] = ffma2(xp, wp[0], acc2[c][0]);
      acc2[c][1] = ffma2(xp, wp[1], acc2[c][1]);
      acc2[c][2] = ffma2(xp, wp[2], acc2[c][2]);
      acc2[c][3] = ffma2(xp, wp[3], acc2[c][3]);
    }
  }
  float acc[NC][8];
#pragma unroll
  for (int c = 0; c < NC; c++)
#pragma unroll
    for (int q = 0; q < 4; q++) unpack2(acc2[c][q], acc[c][2 * q], acc[c][2 * q + 1]);

#pragma unroll
  for (int j = 0; j < 8; j++) {
    float v[NC];
    float m = -3.0e38f;
#pragma unroll
    for (int c = 0; c < NC; c++) {
      v[c] = acc[c][j] + brho[c * NGB + o0 + j];
      m = fmaxf(m, v[c]);
    }
    float e[NC], sum = 0.0f;
#pragma unroll
    for (int c = 0; c < NC; c++) { e[c] = expf(v[c] - m); sum += e[c]; }
    const int base = (b * NGB + o0 + j) * 16;
#pragma unroll
    for (int c = 0; c < NC; c++) {
      const float p = e[c] / sum;
      g_pp[base + c]     = p;
      g_pp[base + 8 + c] = logf(p + 1e-20f);
    }
    g_pp[base + 7] = 0.0f; g_pp[base + 15] = 0.0f;
  }
}

// ---------------------------------------------------------------------------
// K4: Gumbel argmax sampler + mu + pi output
// threefry2x32, key=(0,42), partitionable counters: bits[i] = o0 ^ o1.
// x0-adds routed through IMAD (fma pipe) to relieve the saturated alu pipe.
// ---------------------------------------------------------------------------
__device__ __forceinline__ unsigned tf_bits(unsigned ctr) {
  const unsigned k0 = 0u, k1 = 42u, k2 = 0x1BD11BDAu ^ 0u ^ 42u;
  unsigned x0 = 0u + k0;      // counts_hi = 0
  unsigned x1 = ctr + k1;     // counts_lo = ctr
#define TF_R(r) { x0 = addf(x0, x1); x1 = __funnelshift_l(x1, x1, r); x1 ^= x0; }
  TF_R(13) TF_R(15) TF_R(26) TF_R(6)
  x0 = addf(x0, k1); x1 += k2 + 1u;
  TF_R(17) TF_R(29) TF_R(16) TF_R(24)
  x0 = addf(x0, k2); x1 += k0 + 2u;
  TF_R(13) TF_R(15) TF_R(26) TF_R(6)
  x0 = addf(x0, k0); x1 += k1 + 3u;
  TF_R(17) TF_R(29) TF_R(16) TF_R(24)
  x0 = addf(x0, k1); x1 += k2 + 4u;
  TF_R(13) TF_R(15) TF_R(26) TF_R(6)
  x0 = addf(x0, k2); x1 += k0 + 5u;
#undef TF_R
  return x0 ^ x1;
}

__global__ __launch_bounds__(128) void k_sample(
    const float* __restrict__ wsc, const float* __restrict__ bsc,
    float* __restrict__ out) {
  const int b = blockIdx.y;
  const int g = blockIdx.x * 128 + threadIdx.x;
  if (g >= NG) return;
  const int o = g / 25;
  const float4* pp = (const float4*)&g_pp[(b * NGB + o) * 16];
  const float4 pv0 = __ldg(pp + 0), pv1 = __ldg(pp + 1);
  const float4 lv0 = __ldg(pp + 2), lv1 = __ldg(pp + 3);
  const float p[NC]  = {pv0.x, pv0.y, pv0.z, pv0.w, pv1.x, pv1.y, pv1.z};
  const float lp[NC] = {lv0.x, lv0.y, lv0.z, lv0.w, lv1.x, lv1.y, lv1.z};
  const unsigned i0 = (unsigned)(b * NG + g) * 7u;

  float m = -3.0e38f;
  int cmax = 0;
#pragma unroll
  for (int c = 0; c < NC; c++) {
    const unsigned bits = tf_bits(i0 + (unsigned)c);
    const float u = __uint_as_float((bits >> 9) | 0x3f800000u) - 1.0f;
    const float gn = -__logf(-__logf(u + 1e-20f) + 1e-20f);
    const float sv = lp[c] + gn;      // *10 and softmax are argmax-invariant
    if (sv > m) { m = sv; cmax = c; }
  }
  const float smp = (float)cmax;
  const size_t bg = (size_t)b * NG + g;
  out[OFF_SAMPLE + bg] = smp;
  const float t = smp * wsc[g] + bsc[g];
  out[OFF_MU + bg] = __fdividef(1.0f, 1.0f + __expf(-t));
  float* po = out + OFF_PI + bg * 7;
#pragma unroll
  for (int c = 0; c < NC; c++) po[c] = p[c];
}

// ---------------------------------------------------------------------------
extern "C" void kernel_launch(void* const* d_in, const int* in_sizes, int n_in,
                              void* d_out, int out_size) {
  const float* z   = (const float*)d_in[0];
  const float* w0  = (const float*)d_in[1];
  const float* b0  = (const float*)d_in[2];
  const float* g0  = (const float*)d_in[3];
  const float* be0 = (const float*)d_in[4];
  const float* m0  = (const float*)d_in[5];
  const float* v0  = (const float*)d_in[6];
  const float* w1  = (const float*)d_in[7];
  const float* b1  = (const float*)d_in[8];
  const float* g1  = (const float*)d_in[9];
  const float* be1 = (const float*)d_in[10];
  const float* m1  = (const float*)d_in[11];
  const float* v1  = (const float*)d_in[12];
  const float* wr  = (const float*)d_in[13];
  const float* br  = (const float*)d_in[14];
  const float* wd  = (const float*)d_in[15];
  const float* bd  = (const float*)d_in[16];
  const float* wrho= (const float*)d_in[17];
  const float* brho= (const float*)d_in[18];
  const float* wsc = (const float*)d_in[19];
  const float* bsc = (const float*)d_in[20];
  float* out = (float*)d_out;

  // one-time side stream + fork/join events (created outside capture: the
  // harness runs kernel_launch once for correctness before capturing)
  static cudaStream_t s2 = nullptr;
  static cudaEvent_t evF = nullptr, evJ = nullptr;
  if (!s2) {
    cudaStreamCreateWithFlags(&s2, cudaStreamNonBlocking);
    cudaEventCreateWithFlags(&evF, cudaEventDisableTiming);
    cudaEventCreateWithFlags(&evJ, cudaEventDisableTiming);
  }

  k_mlp<<<NB, HID>>>(z, w0, b0, g0, be0, m0, v0, w1, b1, g1, be1, m1, v1);

  // fork: k_gemm on s2 runs alongside k_rho -> k_sample on the main stream
  cudaEventRecord(evF, 0);
  cudaStreamWaitEvent(s2, evF, 0);
  dim3 gg((NG + BN - 1) / BN, NB / BM);
  k_gemm<<<gg, 256, 0, s2>>>(wr, br, wd, bd, out);
  cudaEventRecord(evJ, s2);

  k_rho<<<NGB / 8, 256>>>(wrho, brho);
  dim3 gs((NG + 127) / 128, NB);
  k_sample<<<gs, 128>>>(wsc, bsc, out);

  // join
  cudaStreamWaitEvent(0, evJ, 0);
}

// round 14
// speedup vs baseline: 1.2648x; 1.0194x over previous
#include <cuda_runtime.h>
#include <cuda_bf16.h>
#include <cstdint>

#define NB   256
#define LAT  20
#define HID  128
#define NG   25000
#define NGB  1000
#define NC   7

// output tuple (mu, theta, pi_drop, sample, pi) concatenated, fp32
#define OFF_MU      0
#define OFF_THETA   6400000
#define OFF_PD      12800000
#define OFF_SAMPLE  19200000
#define OFF_PI      25600000

// scratch (device globals; no allocations allowed)
__device__ __align__(16) float g_xt[HID * NB];   // x^T[h][b]
// per (b,o): floats [0..6]=p, [8..14]=log(p+1e-20), padded to 16 for LDG.128
__device__ __align__(16) float g_pp[NB * NGB * 16];

// ---------------------------------------------------------------------------
// packed fp32x2 helpers (Blackwell FFMA2 — IEEE-exact lanewise, 2 FMA / issue)
// ---------------------------------------------------------------------------
typedef unsigned long long F2;
__device__ __forceinline__ F2 pack2(float lo, float hi) {
  F2 r; asm("mov.b64 %0, {%1, %2};" : "=l"(r) : "f"(lo), "f"(hi)); return r;
}
__device__ __forceinline__ void unpack2(F2 v, float& lo, float& hi) {
  asm("mov.b64 {%0, %1}, %2;" : "=f"(lo), "=f"(hi) : "l"(v));
}
__device__ __forceinline__ F2 ffma2(F2 a, F2 b, F2 c) {
  F2 d; asm("fma.rn.f32x2 %0, %1, %2, %3;" : "=l"(d) : "l"(a), "l"(b), "l"(c));
  return d;
}

// ---------------------------------------------------------------------------
// K1: x = relu(bn(relu(bn(z@w0+b0)) @ w1 + b1)) -> g_xt (k-major)
// ---------------------------------------------------------------------------
__global__ __launch_bounds__(HID) void k_mlp(
    const float* __restrict__ z,  const float* __restrict__ w0,
    const float* __restrict__ b0, const float* __restrict__ g0,
    const float* __restrict__ be0,const float* __restrict__ m0,
    const float* __restrict__ v0,
    const float* __restrict__ w1, const float* __restrict__ b1,
    const float* __restrict__ g1, const float* __restrict__ be1,
    const float* __restrict__ m1, const float* __restrict__ v1) {
  __shared__ float zs[LAT];
  __shared__ float xs[HID];
  const int b = blockIdx.x;
  const int h = threadIdx.x;
  if (h < LAT) zs[h] = z[b * LAT + h];
  __syncthreads();
  float acc = b0[h];
#pragma unroll
  for (int k = 0; k < LAT; k++) acc = fmaf(zs[k], w0[k * HID + h], acc);
  acc = (acc - m0[h]) * rsqrtf(v0[h] + 1e-3f) * g0[h] + be0[h];
  acc = fmaxf(acc, 0.0f);
  xs[h] = acc;
  __syncthreads();
  float a2 = b1[h];
#pragma unroll
  for (int k = 0; k < HID; k++) a2 = fmaf(xs[k], w1[k * HID + h], a2);
  a2 = (a2 - m1[h]) * rsqrtf(v1[h] + 1e-3f) * g1[h] + be1[h];
  a2 = fmaxf(a2, 0.0f);
  g_xt[h * NB + b] = a2;
}

// ---------------------------------------------------------------------------
// K2: theta = exp(x@wr+br), pi_drop = x@wd+bd
// PERSISTENT: 148 blocks (1/SM), each loops over tiles. This guarantees each
// SM co-hosts one fma/LDS-heavy gemm block beside ~10 alu-heavy sample blocks
// so the SMSP arbiter dual-issues across complementary pipes.
// Tile: BM=128 x BN=64 x BK=32, 256 threads, thread tile 8b x 4g x 2 matrices.
// ---------------------------------------------------------------------------
#define BM 128
#define BN 64
#define BK 32
#define NTILE_G 391   // ceil(NG/BN)
#define NTILES  (NTILE_G * (NB / BM))
__global__ __launch_bounds__(256) void k_gemm(
    const float* __restrict__ wr, const float* __restrict__ br,
    const float* __restrict__ wd, const float* __restrict__ bd,
    float* __restrict__ out) {
  __shared__ float xs[BK][BM];    // 16 KB
  __shared__ float wrs[BK][BN];   // 8 KB
  __shared__ float wds[BK][BN];   // 8 KB
  const int tid = threadIdx.x;
  const int tx = tid & 15;        // gene group (4 genes)
  const int ty = tid >> 4;        // batch group (8 batches)

  for (int t = blockIdx.x; t < NTILES; t += gridDim.x) {
    const int g0 = (t % NTILE_G) * BN;
    const int m0 = (t / NTILE_G) * BM;

    F2 aT2[8][2], aD2[8][2];
#pragma unroll
    for (int i = 0; i < 8; i++) {
      aT2[i][0] = aT2[i][1] = 0ull;
      aD2[i][0] = aD2[i][1] = 0ull;
    }

    for (int kc = 0; kc < HID; kc += BK) {
      {
        const int m4 = (tid & 31) * 4;
        const int kk0 = tid >> 5;
#pragma unroll
        for (int tt = 0; tt < 4; tt++) {
          const int kk = kk0 + tt * 8;
          *(float4*)&xs[kk][m4] =
              *(const float4*)&g_xt[(kc + kk) * NB + m0 + m4];
        }
      }
      {
        const int j4 = (tid & 15) * 4;
        const int kk0 = tid >> 4;
#pragma unroll
        for (int tt = 0; tt < 2; tt++) {
          const int kk = kk0 + tt * 16;
          const int g = g0 + j4;
          float4 vr, vd;
          if (g + 3 < NG) {
            vr = *(const float4*)&wr[(size_t)(kc + kk) * NG + g];
            vd = *(const float4*)&wd[(size_t)(kc + kk) * NG + g];
          } else {
            float r[4], d[4];
#pragma unroll
            for (int q = 0; q < 4; q++) {
              const bool ok = (g + q < NG);
              r[q] = ok ? wr[(size_t)(kc + kk) * NG + g + q] : 0.0f;
              d[q] = ok ? wd[(size_t)(kc + kk) * NG + g + q] : 0.0f;
            }
            vr = make_float4(r[0], r[1], r[2], r[3]);
            vd = make_float4(d[0], d[1], d[2], d[3]);
          }
          *(float4*)&wrs[kk][j4] = vr;
          *(float4*)&wds[kk][j4] = vd;
        }
      }
      __syncthreads();
#pragma unroll
      for (int k = 0; k < BK; k++) {
        const float4 a0 = *(const float4*)&xs[k][ty * 8];
        const float4 a1 = *(const float4*)&xs[k][ty * 8 + 4];
        const F2 w0 = *(const F2*)&wrs[k][tx * 4];
        const F2 w1 = *(const F2*)&wrs[k][tx * 4 + 2];
        const F2 d0 = *(const F2*)&wds[k][tx * 4];
        const F2 d1 = *(const F2*)&wds[k][tx * 4 + 2];
        const float a[8] = {a0.x, a0.y, a0.z, a0.w, a1.x, a1.y, a1.z, a1.w};
#pragma unroll
        for (int i = 0; i < 8; i++) {
          const F2 ap = pack2(a[i], a[i]);
          aT2[i][0] = ffma2(ap, w0, aT2[i][0]);
          aT2[i][1] = ffma2(ap, w1, aT2[i][1]);
          aD2[i][0] = ffma2(ap, d0, aD2[i][0]);
          aD2[i][1] = ffma2(ap, d1, aD2[i][1]);
        }
      }
      __syncthreads();
    }

    const int gbase = g0 + tx * 4;
    const bool full = (gbase + 3 < NG);
    float brv[4] = {}, bdv[4] = {};
#pragma unroll
    for (int q = 0; q < 4; q++)
      if (gbase + q < NG) { brv[q] = br[gbase + q]; bdv[q] = bd[gbase + q]; }
#pragma unroll
    for (int i = 0; i < 8; i++) {
      float tv[4], dv[4];
      unpack2(aT2[i][0], tv[0], tv[1]); unpack2(aT2[i][1], tv[2], tv[3]);
      unpack2(aD2[i][0], dv[0], dv[1]); unpack2(aD2[i][1], dv[2], dv[3]);
      const int mrow = m0 + ty * 8 + i;
      const size_t idx = (size_t)mrow * NG + gbase;
      if (full) {
        float4 to = make_float4(__expf(tv[0] + brv[0]), __expf(tv[1] + brv[1]),
                                __expf(tv[2] + brv[2]), __expf(tv[3] + brv[3]));
        float4 po = make_float4(dv[0] + bdv[0], dv[1] + bdv[1],
                                dv[2] + bdv[2], dv[3] + bdv[3]);
        *(float4*)&out[OFF_THETA + idx] = to;
        *(float4*)&out[OFF_PD + idx]    = po;
      } else {
#pragma unroll
        for (int q = 0; q < 4; q++) {
          if (gbase + q >= NG) continue;
          out[OFF_THETA + idx + q] = __expf(tv[q] + brv[q]);
          out[OFF_PD + idx + q]    = dv[q] + bdv[q];
        }
      }
    }
    __syncthreads();   // smem safe for next tile
  }
}

// ---------------------------------------------------------------------------
// K3: rho[c][b][o] = x@wrho[c] + brho[c]; softmax over c; store p / log(p+eps)
// ---------------------------------------------------------------------------
__global__ __launch_bounds__(256) void k_rho(
    const float* __restrict__ wrho, const float* __restrict__ brho) {
  __shared__ float ws[NC * HID * 8];  // 28 KB
  const int tid = threadIdx.x;
  const int b = tid;
  const int o0 = blockIdx.x * 8;
  for (int idx = tid; idx < NC * HID * 8; idx += 256) {
    const int c = idx >> 10;
    const int rem = idx & 1023;
    const int h = rem >> 3, j = rem & 7;
    ws[idx] = wrho[c * HID * NGB + h * NGB + o0 + j];
  }
  __syncthreads();

  F2 acc2[NC][4];
#pragma unroll
  for (int c = 0; c < NC; c++)
#pragma unroll
    for (int q = 0; q < 4; q++) acc2[c][q] = 0ull;

  for (int h = 0; h < HID; h++) {
    const float xv = g_xt[h * NB + b];
    const F2 xp = pack2(xv, xv);
#pragma unroll
    for (int c = 0; c < NC; c++) {
      const F2* wp = (const F2*)&ws[(c * HID + h) * 8];
      acc2[c][0] = ffma2(xp, wp[0], acc2[c][0]);
      acc2[c][1] = ffma2(xp, wp[1], acc2[c][1]);
      acc2[c][2] = ffma2(xp, wp[2], acc2[c][2]);
      acc2[c][3] = ffma2(xp, wp[3], acc2[c][3]);
    }
  }
  float acc[NC][8];
#pragma unroll
  for (int c = 0; c < NC; c++)
#pragma unroll
    for (int q = 0; q < 4; q++) unpack2(acc2[c][q], acc[c][2 * q], acc[c][2 * q + 1]);

#pragma unroll
  for (int j = 0; j < 8; j++) {
    float v[NC];
    float m = -3.0e38f;
#pragma unroll
    for (int c = 0; c < NC; c++) {
      v[c] = acc[c][j] + brho[c * NGB + o0 + j];
      m = fmaxf(m, v[c]);
    }
    float e[NC], sum = 0.0f;
#pragma unroll
    for (int c = 0; c < NC; c++) { e[c] = expf(v[c] - m); sum += e[c]; }
    const int base = (b * NGB + o0 + j) * 16;
#pragma unroll
    for (int c = 0; c < NC; c++) {
      const float p = e[c] / sum;
      g_pp[base + c]     = p;
      g_pp[base + 8 + c] = logf(p + 1e-20f);
    }
    g_pp[base + 7] = 0.0f; g_pp[base + 15] = 0.0f;
  }
}

// ---------------------------------------------------------------------------
// K4: Gumbel argmax sampler + mu + pi output
// threefry2x32, key=(0,42), partitionable counters: bits[i] = o0 ^ o1
// ---------------------------------------------------------------------------
__device__ __forceinline__ unsigned tf_bits(unsigned ctr) {
  const unsigned k0 = 0u, k1 = 42u, k2 = 0x1BD11BDAu ^ 0u ^ 42u;
  unsigned x0 = 0u + k0;
  unsigned x1 = ctr + k1;
#define TF_R(r) { x0 += x1; x1 = __funnelshift_l(x1, x1, r); x1 ^= x0; }
  TF_R(13) TF_R(15) TF_R(26) TF_R(6)   x0 += k1; x1 += k2 + 1u;
  TF_R(17) TF_R(29) TF_R(16) TF_R(24)  x0 += k2; x1 += k0 + 2u;
  TF_R(13) TF_R(15) TF_R(26) TF_R(6)   x0 += k0; x1 += k1 + 3u;
  TF_R(17) TF_R(29) TF_R(16) TF_R(24)  x0 += k1; x1 += k2 + 4u;
  TF_R(13) TF_R(15) TF_R(26) TF_R(6)   x0 += k2; x1 += k0 + 5u;
#undef TF_R
  return x0 ^ x1;
}

__global__ __launch_bounds__(128) void k_sample(
    const float* __restrict__ wsc, const float* __restrict__ bsc,
    float* __restrict__ out) {
  const int b = blockIdx.y;
  const int g = blockIdx.x * 128 + threadIdx.x;
  if (g >= NG) return;
  const int o = g / 25;
  const float4* pp = (const float4*)&g_pp[(b * NGB + o) * 16];
  const float4 pv0 = __ldg(pp + 0), pv1 = __ldg(pp + 1);
  const float4 lv0 = __ldg(pp + 2), lv1 = __ldg(pp + 3);
  const float p[NC]  = {pv0.x, pv0.y, pv0.z, pv0.w, pv1.x, pv1.y, pv1.z};
  const float lp[NC] = {lv0.x, lv0.y, lv0.z, lv0.w, lv1.x, lv1.y, lv1.z};
  const unsigned i0 = (unsigned)(b * NG + g) * 7u;

  float m = -3.0e38f;
  int cmax = 0;
#pragma unroll
  for (int c = 0; c < NC; c++) {
    const unsigned bits = tf_bits(i0 + (unsigned)c);
    const float u = __uint_as_float((bits >> 9) | 0x3f800000u) - 1.0f;
    const float gn = -__logf(-__logf(u + 1e-20f) + 1e-20f);
    const float sv = lp[c] + gn;      // *10 and softmax are argmax-invariant
    if (sv > m) { m = sv; cmax = c; }
  }
  const float smp = (float)cmax;
  const size_t bg = (size_t)b * NG + g;
  out[OFF_SAMPLE + bg] = smp;
  const float t = smp * wsc[g] + bsc[g];
  out[OFF_MU + bg] = __fdividef(1.0f, 1.0f + __expf(-t));
  float* po = out + OFF_PI + bg * 7;
#pragma unroll
  for (int c = 0; c < NC; c++) po[c] = p[c];
}

// ---------------------------------------------------------------------------
extern "C" void kernel_launch(void* const* d_in, const int* in_sizes, int n_in,
                              void* d_out, int out_size) {
  const float* z   = (const float*)d_in[0];
  const float* w0  = (const float*)d_in[1];
  const float* b0  = (const float*)d_in[2];
  const float* g0  = (const float*)d_in[3];
  const float* be0 = (const float*)d_in[4];
  const float* m0  = (const float*)d_in[5];
  const float* v0  = (const float*)d_in[6];
  const float* w1  = (const float*)d_in[7];
  const float* b1  = (const float*)d_in[8];
  const float* g1  = (const float*)d_in[9];
  const float* be1 = (const float*)d_in[10];
  const float* m1  = (const float*)d_in[11];
  const float* v1  = (const float*)d_in[12];
  const float* wr  = (const float*)d_in[13];
  const float* br  = (const float*)d_in[14];
  const float* wd  = (const float*)d_in[15];
  const float* bd  = (const float*)d_in[16];
  const float* wrho= (const float*)d_in[17];
  const float* brho= (const float*)d_in[18];
  const float* wsc = (const float*)d_in[19];
  const float* bsc = (const float*)d_in[20];
  float* out = (float*)d_out;

  // one-time side stream + fork/join events (created outside capture: the
  // harness runs kernel_launch once for correctness before capturing)
  static cudaStream_t s2 = nullptr;
  static cudaEvent_t evF = nullptr, evJ = nullptr;
  if (!s2) {
    cudaStreamCreateWithFlags(&s2, cudaStreamNonBlocking);
    cudaEventCreateWithFlags(&evF, cudaEventDisableTiming);
    cudaEventCreateWithFlags(&evJ, cudaEventDisableTiming);
  }

  k_mlp<<<NB, HID>>>(z, w0, b0, g0, be0, m0, v0, w1, b1, g1, be1, m1, v1);

  // fork: persistent k_gemm (148 blocks = 1/SM) co-resides with rho+sample
  cudaEventRecord(evF, 0);
  cudaStreamWaitEvent(s2, evF, 0);
  k_gemm<<<148, 256, 0, s2>>>(wr, br, wd, bd, out);
  cudaEventRecord(evJ, s2);

  k_rho<<<NGB / 8, 256>>>(wrho, brho);
  dim3 gs((NG + 127) / 128, NB);
  k_sample<<<gs, 128>>>(wsc, bsc, out);

  // join
  cudaStreamWaitEvent(0, evJ, 0);
}